// round 6
// baseline (speedup 1.0000x reference)
#include <cuda_runtime.h>
#include <cstdint>

#define NN   50000
#define EE   800000
#define HIDD 128
#define MLP0 512
#define MLP1 256

// ---------------- scratch (device globals; referenced ONLY from device code) ----------------
__device__ float g_H[(size_t)NN * HIDD];     // GEMM output (pre-aggregation)
__device__ float g_AGG[(size_t)NN * HIDD];   // aggregation output
__device__ float g_M1[(size_t)NN * MLP0];    // MLP hidden
__device__ int   g_cnt[NN + 1];
__device__ int   g_rowptr[NN + 1];
__device__ int   g_fill[NN];
__device__ float g_dinv[NN];
__device__ int   g_csr_src[EE];
__device__ float g_csr_w[EE];
__device__ int   g_is64;

// ---------------- edge_index dtype detection ----------------
// If the buffer really holds int64 indices, the first 64 values (as int64) are
// all in [0, NN). If it holds int32 pairs, the high 32 bits are a second index
// (nonzero w.p. ~1), so the int64 view is >= 2^32 almost surely.
__global__ void detect_kernel(const void* __restrict__ ei) {
    if (threadIdx.x == 0 && blockIdx.x == 0) {
        const long long* p = (const long long*)ei;
        int ok = 1;
        for (int i = 0; i < 64; i++) {
            long long v = p[i];
            if (v < 0 || v >= NN) { ok = 0; break; }
        }
        g_is64 = ok;
    }
}

__device__ __forceinline__ int load_idx(const void* __restrict__ ei, int e, int which) {
    if (g_is64) return (int)((const long long*)ei)[(size_t)which * EE + e];
    return ((const int*)ei)[(size_t)which * EE + e];
}

// ---------------- CSR build ----------------
__global__ void zero_cnt_kernel() {
    int i = blockIdx.x * blockDim.x + threadIdx.x;
    if (i <= NN) g_cnt[i] = 0;
}

__global__ void hist_kernel(const void* __restrict__ ei) {
    int e = blockIdx.x * blockDim.x + threadIdx.x;
    if (e >= EE) return;
    unsigned d = (unsigned)load_idx(ei, e, 1);
    if (d < NN) atomicAdd(&g_cnt[d], 1);
}

__global__ void dinv_kernel() {
    int v = blockIdx.x * blockDim.x + threadIdx.x;
    if (v < NN) g_dinv[v] = rsqrtf((float)(g_cnt[v] + 1));  // +1 self loop
}

// single-block exclusive scan of g_cnt -> g_rowptr (and g_fill running offsets)
__global__ void scan_kernel() {
    __shared__ int sh[1024];
    __shared__ int s_carry;
    int t = threadIdx.x;
    if (t == 0) s_carry = 0;
    __syncthreads();
    for (int base = 0; base < NN; base += 1024) {
        int i = base + t;
        int v = (i < NN) ? g_cnt[i] : 0;
        sh[t] = v;
        __syncthreads();
        for (int off = 1; off < 1024; off <<= 1) {
            int add = (t >= off) ? sh[t - off] : 0;
            __syncthreads();
            sh[t] += add;
            __syncthreads();
        }
        int carry = s_carry;
        int excl = carry + sh[t] - v;
        if (i < NN) { g_rowptr[i] = excl; g_fill[i] = excl; }
        __syncthreads();
        if (t == 0) s_carry = carry + sh[1023];
        __syncthreads();
    }
    if (t == 0) g_rowptr[NN] = s_carry;
}

__global__ void fill_kernel(const void* __restrict__ ei) {
    int e = blockIdx.x * blockDim.x + threadIdx.x;
    if (e >= EE) return;
    unsigned s = (unsigned)load_idx(ei, e, 0);
    unsigned d = (unsigned)load_idx(ei, e, 1);
    if (s >= NN || d >= NN) return;
    int p = atomicAdd(&g_fill[d], 1);
    if (p < EE) {
        g_csr_src[p] = (int)s;
        g_csr_w[p]   = g_dinv[s] * g_dinv[d];
    }
}

// ---------------- pull-model aggregation: one warp per dst node ----------------
// g_AGG[v] = dinv[v]^2 * g_H[v] + sum_{e: dst=v} w_e * g_H[src_e]
__global__ void agg_kernel() {
    const float* __restrict__ H = g_H;
    int gw   = (blockIdx.x * blockDim.x + threadIdx.x) >> 5;
    int lane = threadIdx.x & 31;
    if (gw >= NN) return;
    float sw = g_dinv[gw];
    sw *= sw;  // self-loop norm
    float4 a = ((const float4*)(H + (size_t)gw * HIDD))[lane];
    a.x *= sw; a.y *= sw; a.z *= sw; a.w *= sw;
    int beg = g_rowptr[gw], end = g_rowptr[gw + 1];
    for (int e = beg; e < end; e++) {
        int   s  = g_csr_src[e];
        float wv = g_csr_w[e];
        float4 h4 = ((const float4*)(H + (size_t)s * HIDD))[lane];
        a.x = fmaf(h4.x, wv, a.x);
        a.y = fmaf(h4.y, wv, a.y);
        a.z = fmaf(h4.z, wv, a.z);
        a.w = fmaf(h4.w, wv, a.w);
    }
    ((float4*)(g_AGG + (size_t)gw * HIDD))[lane] = a;
}

// ---------------- fp32 tiled GEMM: C = act(A) @ W (+post bias/relu) ----------------
// A/C selection is compile-time: 0 = kernel argument, 1 = g_H, 2 = g_AGG, 3 = g_M1.
// Scratch buffers never cross the host/device parameter boundary.
// PRE:  a = relu(A + preb[k])   POST: c = relu(c + postb[n])
template <int K, bool PRE, bool POST, int ASEL, int CSEL>
__global__ void __launch_bounds__(256)
gemm_kernel(const float* __restrict__ Aarg, const float* __restrict__ W,
            const float* __restrict__ preb, const float* __restrict__ postb,
            float* __restrict__ Carg, int M, int Nout) {
    const float* A = (ASEL == 1) ? g_H : (ASEL == 2) ? g_AGG : (ASEL == 3) ? g_M1 : Aarg;
    float*       C = (CSEL == 1) ? g_H : (CSEL == 2) ? g_AGG : (CSEL == 3) ? g_M1 : Carg;

    const int BM = 64, BN = 64, BK = 32;
    __shared__ float As[BK][BM + 4];  // stored K-major (transposed) for float4 reads
    __shared__ float Ws[BK][BN + 4];

    int tid = threadIdx.x;
    int tx = tid & 15, ty = tid >> 4;
    int row0 = blockIdx.x * BM;
    int col0 = blockIdx.y * BN;

    int ar = tid >> 3, aq = tid & 7;    // A loader: row(0..31), quad(0..7)
    int wr = tid >> 4, wq = tid & 15;   // W loader: row(0..15), quad(0..15)

    float acc[4][4];
#pragma unroll
    for (int i = 0; i < 4; i++)
#pragma unroll
        for (int j = 0; j < 4; j++) acc[i][j] = 0.f;

    for (int k0 = 0; k0 < K; k0 += BK) {
#pragma unroll
        for (int h = 0; h < 2; h++) {
            int r = ar + h * 32;
            int grow = row0 + r;
            float4 v = make_float4(0.f, 0.f, 0.f, 0.f);
            if (grow < M) v = *(const float4*)(A + (size_t)grow * K + k0 + aq * 4);
            if (PRE) {
                v.x = fmaxf(v.x + preb[k0 + aq * 4 + 0], 0.f);
                v.y = fmaxf(v.y + preb[k0 + aq * 4 + 1], 0.f);
                v.z = fmaxf(v.z + preb[k0 + aq * 4 + 2], 0.f);
                v.w = fmaxf(v.w + preb[k0 + aq * 4 + 3], 0.f);
            }
            As[aq * 4 + 0][r] = v.x;
            As[aq * 4 + 1][r] = v.y;
            As[aq * 4 + 2][r] = v.z;
            As[aq * 4 + 3][r] = v.w;
        }
#pragma unroll
        for (int h = 0; h < 2; h++) {
            int r = wr + h * 16;
            float4 v = *(const float4*)(W + (size_t)(k0 + r) * Nout + col0 + wq * 4);
            *(float4*)&Ws[r][wq * 4] = v;
        }
        __syncthreads();
#pragma unroll
        for (int kk = 0; kk < BK; kk++) {
            float4 av = *(const float4*)&As[kk][ty * 4];
            float4 wv = *(const float4*)&Ws[kk][tx * 4];
            float a4[4] = {av.x, av.y, av.z, av.w};
            float w4[4] = {wv.x, wv.y, wv.z, wv.w};
#pragma unroll
            for (int i = 0; i < 4; i++)
#pragma unroll
                for (int j = 0; j < 4; j++) acc[i][j] = fmaf(a4[i], w4[j], acc[i][j]);
        }
        __syncthreads();
    }

#pragma unroll
    for (int i = 0; i < 4; i++) {
        int grow = row0 + ty * 4 + i;
        if (grow < M) {
            float4 v = make_float4(acc[i][0], acc[i][1], acc[i][2], acc[i][3]);
            if (POST) {
                v.x = fmaxf(v.x + postb[col0 + tx * 4 + 0], 0.f);
                v.y = fmaxf(v.y + postb[col0 + tx * 4 + 1], 0.f);
                v.z = fmaxf(v.z + postb[col0 + tx * 4 + 2], 0.f);
                v.w = fmaxf(v.w + postb[col0 + tx * 4 + 3], 0.f);
            }
            *(float4*)(C + (size_t)grow * Nout + col0 + tx * 4) = v;
        }
    }
}

// ---------------- launch: ONLY kernel launches, no other CUDA API ----------------
extern "C" void kernel_launch(void* const* d_in, const int* in_sizes, int n_in,
                              void* d_out, int out_size) {
    const float* x   = (const float*)d_in[0];
    const void*  ei  = d_in[1];  // int32 or int64 indices; detected on device
    const float* Wg0 = (const float*)d_in[2];
    const float* bg0 = (const float*)d_in[3];
    const float* Wg1 = (const float*)d_in[4];
    const float* bg1 = (const float*)d_in[5];
    const float* Wg2 = (const float*)d_in[6];
    const float* bg2 = (const float*)d_in[7];
    const float* Wm0 = (const float*)d_in[8];
    const float* bm0 = (const float*)d_in[9];
    const float* Wm1 = (const float*)d_in[10];
    const float* bm1 = (const float*)d_in[11];
    float*       out = (float*)d_out;

    // --- CSR build (per launch; cheap) ---
    detect_kernel<<<1, 32>>>(ei);
    zero_cnt_kernel<<<(NN + 256) / 256, 256>>>();
    hist_kernel<<<(EE + 255) / 256, 256>>>(ei);
    dinv_kernel<<<(NN + 255) / 256, 256>>>();
    scan_kernel<<<1, 1024>>>();
    fill_kernel<<<(EE + 255) / 256, 256>>>(ei);

    dim3 blk(256);
    dim3 g128((NN + 63) / 64, 2);
    dim3 g512((NN + 63) / 64, 8);
    dim3 g256((NN + 63) / 64, 4);
    int aggBlocks = (NN * 32 + 255) / 256;

    // GCN layer 0: g_H = x @ Wg0 ; g_AGG = Ahat g_H
    gemm_kernel<128, false, false, 0, 1><<<g128, blk>>>(x, Wg0, nullptr, nullptr, nullptr, NN, HIDD);
    agg_kernel<<<aggBlocks, 256>>>();
    // GCN layer 1: g_H = relu(g_AGG + bg0) @ Wg1 ; g_AGG = Ahat g_H
    gemm_kernel<128, true, false, 2, 1><<<g128, blk>>>(nullptr, Wg1, bg0, nullptr, nullptr, NN, HIDD);
    agg_kernel<<<aggBlocks, 256>>>();
    // GCN layer 2: g_H = relu(g_AGG + bg1) @ Wg2 ; g_AGG = Ahat g_H
    gemm_kernel<128, true, false, 2, 1><<<g128, blk>>>(nullptr, Wg2, bg1, nullptr, nullptr, NN, HIDD);
    agg_kernel<<<aggBlocks, 256>>>();
    // MLP: g_M1 = relu(relu(g_AGG + bg2) @ Wm0 + bm0)
    gemm_kernel<128, true, true, 2, 3><<<g512, blk>>>(nullptr, Wm0, bg2, bm0, nullptr, NN, MLP0);
    // out = relu(g_M1 @ Wm1 + bm1)
    gemm_kernel<512, false, true, 3, 0><<<g256, blk>>>(nullptr, Wm1, nullptr, bm1, out, NN, MLP1);
}

// round 7
// speedup vs baseline: 1.0173x; 1.0173x over previous
#include <cuda_runtime.h>
#include <cstdint>

#define NN   50000
#define EE   800000
#define HIDD 128
#define MLP0 512
#define MLP1 256

// ---------------- scratch (device globals; referenced ONLY from device code) ----------------
__device__ float g_H[(size_t)NN * HIDD];     // GEMM output (pre-aggregation)
__device__ float g_AGG[(size_t)NN * HIDD];   // aggregation output
__device__ float g_M1[(size_t)NN * MLP0];    // MLP hidden
__device__ int   g_cnt[NN + 1];
__device__ int   g_rowptr[NN + 1];
__device__ int   g_fill[NN];
__device__ float g_dinv[NN];
__device__ int   g_csr_src[EE];
__device__ float g_csr_w[EE];
__device__ int   g_is64;

// ---------------- edge_index dtype detection ----------------
__global__ void detect_kernel(const void* __restrict__ ei) {
    if (threadIdx.x == 0 && blockIdx.x == 0) {
        const long long* p = (const long long*)ei;
        int ok = 1;
        for (int i = 0; i < 64; i++) {
            long long v = p[i];
            if (v < 0 || v >= NN) { ok = 0; break; }
        }
        g_is64 = ok;
    }
}

__device__ __forceinline__ int load_idx(const void* __restrict__ ei, int e, int which) {
    if (g_is64) return (int)((const long long*)ei)[(size_t)which * EE + e];
    return ((const int*)ei)[(size_t)which * EE + e];
}

// ---------------- CSR build ----------------
__global__ void zero_cnt_kernel() {
    int i = blockIdx.x * blockDim.x + threadIdx.x;
    if (i <= NN) g_cnt[i] = 0;
}

__global__ void hist_kernel(const void* __restrict__ ei) {
    int e = blockIdx.x * blockDim.x + threadIdx.x;
    if (e >= EE) return;
    unsigned d = (unsigned)load_idx(ei, e, 1);
    if (d < NN) atomicAdd(&g_cnt[d], 1);
}

__global__ void dinv_kernel() {
    int v = blockIdx.x * blockDim.x + threadIdx.x;
    if (v < NN) g_dinv[v] = rsqrtf((float)(g_cnt[v] + 1));  // +1 self loop
}

__global__ void scan_kernel() {
    __shared__ int sh[1024];
    __shared__ int s_carry;
    int t = threadIdx.x;
    if (t == 0) s_carry = 0;
    __syncthreads();
    for (int base = 0; base < NN; base += 1024) {
        int i = base + t;
        int v = (i < NN) ? g_cnt[i] : 0;
        sh[t] = v;
        __syncthreads();
        for (int off = 1; off < 1024; off <<= 1) {
            int add = (t >= off) ? sh[t - off] : 0;
            __syncthreads();
            sh[t] += add;
            __syncthreads();
        }
        int carry = s_carry;
        int excl = carry + sh[t] - v;
        if (i < NN) { g_rowptr[i] = excl; g_fill[i] = excl; }
        __syncthreads();
        if (t == 0) s_carry = carry + sh[1023];
        __syncthreads();
    }
    if (t == 0) g_rowptr[NN] = s_carry;
}

__global__ void fill_kernel(const void* __restrict__ ei) {
    int e = blockIdx.x * blockDim.x + threadIdx.x;
    if (e >= EE) return;
    unsigned s = (unsigned)load_idx(ei, e, 0);
    unsigned d = (unsigned)load_idx(ei, e, 1);
    if (s >= NN || d >= NN) return;
    int p = atomicAdd(&g_fill[d], 1);
    if (p < EE) {
        g_csr_src[p] = (int)s;
        g_csr_w[p]   = g_dinv[s] * g_dinv[d];
    }
}

// ---------------- pull-model aggregation: one warp per dst node ----------------
__global__ void agg_kernel() {
    const float* __restrict__ H = g_H;
    int gw   = (blockIdx.x * blockDim.x + threadIdx.x) >> 5;
    int lane = threadIdx.x & 31;
    if (gw >= NN) return;
    float sw = g_dinv[gw];
    sw *= sw;  // self-loop norm
    float4 a = ((const float4*)(H + (size_t)gw * HIDD))[lane];
    a.x *= sw; a.y *= sw; a.z *= sw; a.w *= sw;
    int beg = g_rowptr[gw], end = g_rowptr[gw + 1];
    for (int e = beg; e < end; e++) {
        int   s  = g_csr_src[e];
        float wv = g_csr_w[e];
        float4 h4 = ((const float4*)(H + (size_t)s * HIDD))[lane];
        a.x = fmaf(h4.x, wv, a.x);
        a.y = fmaf(h4.y, wv, a.y);
        a.z = fmaf(h4.z, wv, a.z);
        a.w = fmaf(h4.w, wv, a.w);
    }
    ((float4*)(g_AGG + (size_t)gw * HIDD))[lane] = a;
}

// ---------------- fp32 GEMM, 128x128 tile, 8x8 per thread ----------------
// Compute intensity 1.0 FMA/LDS-byte: FFMA pipe and LSU saturate together.
// ASEL/CSEL: 0 = kernel argument, 1 = g_H, 2 = g_AGG, 3 = g_M1.
// PRE:  a = relu(A + preb[k])   POST: c = relu(c + postb[n])
template <int K, bool PRE, bool POST, int ASEL, int CSEL>
__global__ void __launch_bounds__(256, 2)
gemm_kernel(const float* __restrict__ Aarg, const float* __restrict__ W,
            const float* __restrict__ preb, const float* __restrict__ postb,
            float* __restrict__ Carg, int M, int Nout) {
    const float* A = (ASEL == 1) ? g_H : (ASEL == 2) ? g_AGG : (ASEL == 3) ? g_M1 : Aarg;
    float*       C = (CSEL == 1) ? g_H : (CSEL == 2) ? g_AGG : (CSEL == 3) ? g_M1 : Carg;

    const int BM = 128, BN = 128, BK = 16;
    __shared__ float As[BK][BM];   // K-major (transposed) A tile
    __shared__ float Ws[BK][BN];   // row-major W tile

    int tid = threadIdx.x;
    int tx = tid & 15, ty = tid >> 4;       // 16x16 thread grid
    int row0 = blockIdx.x * BM;
    int col0 = blockIdx.y * BN;

    float acc[8][8];
#pragma unroll
    for (int i = 0; i < 8; i++)
#pragma unroll
        for (int j = 0; j < 8; j++) acc[i][j] = 0.f;

    for (int k0 = 0; k0 < K; k0 += BK) {
        // A tile: 128 rows x 16 k = 512 float4 slots, 2 per thread
#pragma unroll
        for (int h = 0; h < 2; h++) {
            int idx = tid + h * 256;
            int r  = idx & 127;
            int kq = idx >> 7;           // 0..3 (float4 chunk along K)
            int grow = row0 + r;
            float4 v = make_float4(0.f, 0.f, 0.f, 0.f);
            if (grow < M) v = *(const float4*)(A + (size_t)grow * K + k0 + kq * 4);
            if (PRE) {
                v.x = fmaxf(v.x + preb[k0 + kq * 4 + 0], 0.f);
                v.y = fmaxf(v.y + preb[k0 + kq * 4 + 1], 0.f);
                v.z = fmaxf(v.z + preb[k0 + kq * 4 + 2], 0.f);
                v.w = fmaxf(v.w + preb[k0 + kq * 4 + 3], 0.f);
            }
            As[kq * 4 + 0][r] = v.x;
            As[kq * 4 + 1][r] = v.y;
            As[kq * 4 + 2][r] = v.z;
            As[kq * 4 + 3][r] = v.w;
        }
        // W tile: 16 k-rows x 128 cols = 512 float4 slots, 2 per thread
#pragma unroll
        for (int h = 0; h < 2; h++) {
            int idx = tid + h * 256;
            int cq = idx & 31;           // 0..31 (float4 chunk along N)
            int r  = idx >> 5;           // 0..15
            float4 v = *(const float4*)(W + (size_t)(k0 + r) * Nout + col0 + cq * 4);
            *(float4*)&Ws[r][cq * 4] = v;
        }
        __syncthreads();
#pragma unroll
        for (int kk = 0; kk < BK; kk++) {
            float a[8], w[8];
            float4 a0 = *(const float4*)&As[kk][ty * 8];
            float4 a1 = *(const float4*)&As[kk][ty * 8 + 4];
            float4 w0 = *(const float4*)&Ws[kk][tx * 8];
            float4 w1 = *(const float4*)&Ws[kk][tx * 8 + 4];
            a[0] = a0.x; a[1] = a0.y; a[2] = a0.z; a[3] = a0.w;
            a[4] = a1.x; a[5] = a1.y; a[6] = a1.z; a[7] = a1.w;
            w[0] = w0.x; w[1] = w0.y; w[2] = w0.z; w[3] = w0.w;
            w[4] = w1.x; w[5] = w1.y; w[6] = w1.z; w[7] = w1.w;
#pragma unroll
            for (int i = 0; i < 8; i++)
#pragma unroll
                for (int j = 0; j < 8; j++) acc[i][j] = fmaf(a[i], w[j], acc[i][j]);
        }
        __syncthreads();
    }

    // epilogue: 8 rows x 8 cols per thread (two float4 per row)
#pragma unroll
    for (int i = 0; i < 8; i++) {
        int grow = row0 + ty * 8 + i;
        if (grow < M) {
#pragma unroll
            for (int q = 0; q < 2; q++) {
                int gcol = col0 + tx * 8 + q * 4;
                float4 v = make_float4(acc[i][q * 4 + 0], acc[i][q * 4 + 1],
                                       acc[i][q * 4 + 2], acc[i][q * 4 + 3]);
                if (POST) {
                    v.x = fmaxf(v.x + postb[gcol + 0], 0.f);
                    v.y = fmaxf(v.y + postb[gcol + 1], 0.f);
                    v.z = fmaxf(v.z + postb[gcol + 2], 0.f);
                    v.w = fmaxf(v.w + postb[gcol + 3], 0.f);
                }
                *(float4*)(C + (size_t)grow * Nout + gcol) = v;
            }
        }
    }
}

// ---------------- launch: ONLY kernel launches, no other CUDA API ----------------
extern "C" void kernel_launch(void* const* d_in, const int* in_sizes, int n_in,
                              void* d_out, int out_size) {
    const float* x   = (const float*)d_in[0];
    const void*  ei  = d_in[1];  // int32 or int64 indices; detected on device
    const float* Wg0 = (const float*)d_in[2];
    const float* bg0 = (const float*)d_in[3];
    const float* Wg1 = (const float*)d_in[4];
    const float* bg1 = (const float*)d_in[5];
    const float* Wg2 = (const float*)d_in[6];
    const float* bg2 = (const float*)d_in[7];
    const float* Wm0 = (const float*)d_in[8];
    const float* bm0 = (const float*)d_in[9];
    const float* Wm1 = (const float*)d_in[10];
    const float* bm1 = (const float*)d_in[11];
    float*       out = (float*)d_out;

    // --- CSR build (per launch; cheap) ---
    detect_kernel<<<1, 32>>>(ei);
    zero_cnt_kernel<<<(NN + 256) / 256, 256>>>();
    hist_kernel<<<(EE + 255) / 256, 256>>>(ei);
    dinv_kernel<<<(NN + 255) / 256, 256>>>();
    scan_kernel<<<1, 1024>>>();
    fill_kernel<<<(EE + 255) / 256, 256>>>(ei);

    dim3 blk(256);
    const int MB = (NN + 127) / 128;           // 391 row-tiles
    dim3 g128(MB, 1);                          // N=128
    dim3 g512(MB, 4);                          // N=512
    dim3 g256(MB, 2);                          // N=256
    int aggBlocks = (NN * 32 + 255) / 256;

    // GCN layer 0: g_H = x @ Wg0 ; g_AGG = Ahat g_H
    gemm_kernel<128, false, false, 0, 1><<<g128, blk>>>(x, Wg0, nullptr, nullptr, nullptr, NN, HIDD);
    agg_kernel<<<aggBlocks, 256>>>();
    // GCN layer 1: g_H = relu(g_AGG + bg0) @ Wg1 ; g_AGG = Ahat g_H
    gemm_kernel<128, true, false, 2, 1><<<g128, blk>>>(nullptr, Wg1, bg0, nullptr, nullptr, NN, HIDD);
    agg_kernel<<<aggBlocks, 256>>>();
    // GCN layer 2: g_H = relu(g_AGG + bg1) @ Wg2 ; g_AGG = Ahat g_H
    gemm_kernel<128, true, false, 2, 1><<<g128, blk>>>(nullptr, Wg2, bg1, nullptr, nullptr, NN, HIDD);
    agg_kernel<<<aggBlocks, 256>>>();
    // MLP: g_M1 = relu(relu(g_AGG + bg2) @ Wm0 + bm0)
    gemm_kernel<128, true, true, 2, 3><<<g512, blk>>>(nullptr, Wm0, bg2, bm0, nullptr, NN, MLP0);
    // out = relu(g_M1 @ Wm1 + bm1)
    gemm_kernel<512, false, true, 3, 0><<<g256, blk>>>(nullptr, Wm1, nullptr, bm1, out, NN, MLP1);
}

// round 8
// speedup vs baseline: 1.1032x; 1.0845x over previous
#include <cuda_runtime.h>
#include <cstdint>

#define NN   50000
#define EE   800000
#define HIDD 128
#define MLP0 512
#define MLP1 256

// ---------------- scratch (device globals; referenced ONLY from device code) ----------------
__device__ float g_H[(size_t)NN * HIDD];
__device__ float g_AGG[(size_t)NN * HIDD];
__device__ float g_M1[(size_t)NN * MLP0];
__device__ int   g_cnt[NN + 1];
__device__ int   g_rowptr[NN + 1];
__device__ int   g_fill[NN];
__device__ float g_dinv[NN];
__device__ int   g_csr_src[EE];
__device__ float g_csr_w[EE];
__device__ int   g_is64;
__device__ int   g_bsum[256];
__device__ int   g_boff[256];

#define SCAN_B 256
#define SCAN_NB ((NN + SCAN_B - 1) / SCAN_B)   // 196

// ---------------- edge_index dtype detection ----------------
__global__ void detect_kernel(const void* __restrict__ ei) {
    if (threadIdx.x == 0 && blockIdx.x == 0) {
        const long long* p = (const long long*)ei;
        int ok = 1;
#pragma unroll
        for (int i = 0; i < 16; i++) {
            long long v = p[i];
            if (v < 0 || v >= NN) ok = 0;
        }
        g_is64 = ok;
    }
}

__device__ __forceinline__ int load_idx(const void* __restrict__ ei, int e, int which) {
    if (g_is64) return (int)((const long long*)ei)[(size_t)which * EE + e];
    return ((const int*)ei)[(size_t)which * EE + e];
}

// ---------------- CSR build ----------------
__global__ void zero_cnt_kernel() {
    int i = blockIdx.x * blockDim.x + threadIdx.x;
    if (i <= NN) g_cnt[i] = 0;
}

__global__ void hist_kernel(const void* __restrict__ ei) {
    int e = blockIdx.x * blockDim.x + threadIdx.x;
    if (e >= EE) return;
    unsigned d = (unsigned)load_idx(ei, e, 1);
    if (d < NN) atomicAdd(&g_cnt[d], 1);
}

__global__ void dinv_kernel() {
    int v = blockIdx.x * blockDim.x + threadIdx.x;
    if (v < NN) g_dinv[v] = rsqrtf((float)(g_cnt[v] + 1));  // +1 self loop
}

// ---- hierarchical exclusive scan: 3 small kernels, full-chip parallel ----
__global__ void scan1_kernel() {
    __shared__ int sh[SCAN_B];
    int t = threadIdx.x, i = blockIdx.x * SCAN_B + t;
    int v = (i < NN) ? g_cnt[i] : 0;
    sh[t] = v;
    __syncthreads();
    for (int off = 1; off < SCAN_B; off <<= 1) {
        int add = (t >= off) ? sh[t - off] : 0;
        __syncthreads();
        sh[t] += add;
        __syncthreads();
    }
    if (i < NN) g_rowptr[i] = sh[t] - v;        // local exclusive
    if (t == SCAN_B - 1) g_bsum[blockIdx.x] = sh[SCAN_B - 1];
}

__global__ void scan2_kernel() {
    __shared__ int sh[256];
    int t = threadIdx.x;
    int v = (t < SCAN_NB) ? g_bsum[t] : 0;
    sh[t] = v;
    __syncthreads();
    for (int off = 1; off < 256; off <<= 1) {
        int add = (t >= off) ? sh[t - off] : 0;
        __syncthreads();
        sh[t] += add;
        __syncthreads();
    }
    if (t < SCAN_NB) g_boff[t] = sh[t] - v;     // exclusive block offsets
    if (t == 255) g_rowptr[NN] = sh[255];       // total
}

__global__ void scan3_kernel() {
    int t = threadIdx.x, i = blockIdx.x * SCAN_B + t;
    if (i < NN) {
        int r = g_rowptr[i] + g_boff[blockIdx.x];
        g_rowptr[i] = r;
        g_fill[i]   = r;
    }
}

__global__ void fill_kernel(const void* __restrict__ ei) {
    int e = blockIdx.x * blockDim.x + threadIdx.x;
    if (e >= EE) return;
    unsigned s = (unsigned)load_idx(ei, e, 0);
    unsigned d = (unsigned)load_idx(ei, e, 1);
    if (s >= NN || d >= NN) return;
    int p = atomicAdd(&g_fill[d], 1);
    if (p < EE) {
        g_csr_src[p] = (int)s;
        g_csr_w[p]   = g_dinv[s] * g_dinv[d];
    }
}

// ---------------- pull aggregation: one warp per dst, 8-way edge unroll ----------------
// Batching 8 independent gathers per iteration raises MLP from ~1 to ~8,
// hiding the ~240cyc L2 latency -> L2-BW bound.
__global__ void agg_kernel() {
    const float4* __restrict__ H4 = (const float4*)g_H;
    int gw   = (blockIdx.x * blockDim.x + threadIdx.x) >> 5;
    int lane = threadIdx.x & 31;
    if (gw >= NN) return;
    float sw = g_dinv[gw];
    sw *= sw;  // self-loop norm
    float4 a = H4[(size_t)gw * 32 + lane];
    a.x *= sw; a.y *= sw; a.z *= sw; a.w *= sw;
    int e = g_rowptr[gw], end = g_rowptr[gw + 1];

    for (; e + 8 <= end; e += 8) {
        int   s0 = g_csr_src[e + 0], s1 = g_csr_src[e + 1];
        int   s2 = g_csr_src[e + 2], s3 = g_csr_src[e + 3];
        int   s4 = g_csr_src[e + 4], s5 = g_csr_src[e + 5];
        int   s6 = g_csr_src[e + 6], s7 = g_csr_src[e + 7];
        float w0 = g_csr_w[e + 0], w1 = g_csr_w[e + 1];
        float w2 = g_csr_w[e + 2], w3 = g_csr_w[e + 3];
        float w4 = g_csr_w[e + 4], w5 = g_csr_w[e + 5];
        float w6 = g_csr_w[e + 6], w7 = g_csr_w[e + 7];
        float4 h0 = H4[(size_t)s0 * 32 + lane];
        float4 h1 = H4[(size_t)s1 * 32 + lane];
        float4 h2 = H4[(size_t)s2 * 32 + lane];
        float4 h3 = H4[(size_t)s3 * 32 + lane];
        float4 h4 = H4[(size_t)s4 * 32 + lane];
        float4 h5 = H4[(size_t)s5 * 32 + lane];
        float4 h6 = H4[(size_t)s6 * 32 + lane];
        float4 h7 = H4[(size_t)s7 * 32 + lane];
        a.x = fmaf(h0.x, w0, a.x); a.y = fmaf(h0.y, w0, a.y); a.z = fmaf(h0.z, w0, a.z); a.w = fmaf(h0.w, w0, a.w);
        a.x = fmaf(h1.x, w1, a.x); a.y = fmaf(h1.y, w1, a.y); a.z = fmaf(h1.z, w1, a.z); a.w = fmaf(h1.w, w1, a.w);
        a.x = fmaf(h2.x, w2, a.x); a.y = fmaf(h2.y, w2, a.y); a.z = fmaf(h2.z, w2, a.z); a.w = fmaf(h2.w, w2, a.w);
        a.x = fmaf(h3.x, w3, a.x); a.y = fmaf(h3.y, w3, a.y); a.z = fmaf(h3.z, w3, a.z); a.w = fmaf(h3.w, w3, a.w);
        a.x = fmaf(h4.x, w4, a.x); a.y = fmaf(h4.y, w4, a.y); a.z = fmaf(h4.z, w4, a.z); a.w = fmaf(h4.w, w4, a.w);
        a.x = fmaf(h5.x, w5, a.x); a.y = fmaf(h5.y, w5, a.y); a.z = fmaf(h5.z, w5, a.z); a.w = fmaf(h5.w, w5, a.w);
        a.x = fmaf(h6.x, w6, a.x); a.y = fmaf(h6.y, w6, a.y); a.z = fmaf(h6.z, w6, a.z); a.w = fmaf(h6.w, w6, a.w);
        a.x = fmaf(h7.x, w7, a.x); a.y = fmaf(h7.y, w7, a.y); a.z = fmaf(h7.z, w7, a.z); a.w = fmaf(h7.w, w7, a.w);
    }
    for (; e < end; e++) {
        int   s  = g_csr_src[e];
        float wv = g_csr_w[e];
        float4 h = H4[(size_t)s * 32 + lane];
        a.x = fmaf(h.x, wv, a.x);
        a.y = fmaf(h.y, wv, a.y);
        a.z = fmaf(h.z, wv, a.z);
        a.w = fmaf(h.w, wv, a.w);
    }
    ((float4*)g_AGG)[(size_t)gw * 32 + lane] = a;
}

// ---------------- fp32 GEMM, 128x128 tile, 8x8 per thread ----------------
// ASEL/CSEL: 0 = kernel argument, 1 = g_H, 2 = g_AGG, 3 = g_M1.
// PRE:  a = relu(A + preb[k])   POST: c = relu(c + postb[n])
template <int K, bool PRE, bool POST, int ASEL, int CSEL>
__global__ void __launch_bounds__(256, 2)
gemm_kernel(const float* __restrict__ Aarg, const float* __restrict__ W,
            const float* __restrict__ preb, const float* __restrict__ postb,
            float* __restrict__ Carg, int M, int Nout) {
    const float* A = (ASEL == 1) ? g_H : (ASEL == 2) ? g_AGG : (ASEL == 3) ? g_M1 : Aarg;
    float*       C = (CSEL == 1) ? g_H : (CSEL == 2) ? g_AGG : (CSEL == 3) ? g_M1 : Carg;

    const int BM = 128, BN = 128, BK = 16;
    __shared__ float As[BK][BM];
    __shared__ float Ws[BK][BN];

    int tid = threadIdx.x;
    int tx = tid & 15, ty = tid >> 4;
    int row0 = blockIdx.x * BM;
    int col0 = blockIdx.y * BN;

    float acc[8][8];
#pragma unroll
    for (int i = 0; i < 8; i++)
#pragma unroll
        for (int j = 0; j < 8; j++) acc[i][j] = 0.f;

    for (int k0 = 0; k0 < K; k0 += BK) {
#pragma unroll
        for (int h = 0; h < 2; h++) {
            int idx = tid + h * 256;
            int r  = idx & 127;
            int kq = idx >> 7;
            int grow = row0 + r;
            float4 v = make_float4(0.f, 0.f, 0.f, 0.f);
            if (grow < M) v = *(const float4*)(A + (size_t)grow * K + k0 + kq * 4);
            if (PRE) {
                v.x = fmaxf(v.x + preb[k0 + kq * 4 + 0], 0.f);
                v.y = fmaxf(v.y + preb[k0 + kq * 4 + 1], 0.f);
                v.z = fmaxf(v.z + preb[k0 + kq * 4 + 2], 0.f);
                v.w = fmaxf(v.w + preb[k0 + kq * 4 + 3], 0.f);
            }
            As[kq * 4 + 0][r] = v.x;
            As[kq * 4 + 1][r] = v.y;
            As[kq * 4 + 2][r] = v.z;
            As[kq * 4 + 3][r] = v.w;
        }
#pragma unroll
        for (int h = 0; h < 2; h++) {
            int idx = tid + h * 256;
            int cq = idx & 31;
            int r  = idx >> 5;
            float4 v = *(const float4*)(W + (size_t)(k0 + r) * Nout + col0 + cq * 4);
            *(float4*)&Ws[r][cq * 4] = v;
        }
        __syncthreads();
#pragma unroll
        for (int kk = 0; kk < BK; kk++) {
            float a[8], w[8];
            float4 a0 = *(const float4*)&As[kk][ty * 8];
            float4 a1 = *(const float4*)&As[kk][ty * 8 + 4];
            float4 w0 = *(const float4*)&Ws[kk][tx * 8];
            float4 w1 = *(const float4*)&Ws[kk][tx * 8 + 4];
            a[0] = a0.x; a[1] = a0.y; a[2] = a0.z; a[3] = a0.w;
            a[4] = a1.x; a[5] = a1.y; a[6] = a1.z; a[7] = a1.w;
            w[0] = w0.x; w[1] = w0.y; w[2] = w0.z; w[3] = w0.w;
            w[4] = w1.x; w[5] = w1.y; w[6] = w1.z; w[7] = w1.w;
#pragma unroll
            for (int i = 0; i < 8; i++)
#pragma unroll
                for (int j = 0; j < 8; j++) acc[i][j] = fmaf(a[i], w[j], acc[i][j]);
        }
        __syncthreads();
    }

#pragma unroll
    for (int i = 0; i < 8; i++) {
        int grow = row0 + ty * 8 + i;
        if (grow < M) {
#pragma unroll
            for (int q = 0; q < 2; q++) {
                int gcol = col0 + tx * 8 + q * 4;
                float4 v = make_float4(acc[i][q * 4 + 0], acc[i][q * 4 + 1],
                                       acc[i][q * 4 + 2], acc[i][q * 4 + 3]);
                if (POST) {
                    v.x = fmaxf(v.x + postb[gcol + 0], 0.f);
                    v.y = fmaxf(v.y + postb[gcol + 1], 0.f);
                    v.z = fmaxf(v.z + postb[gcol + 2], 0.f);
                    v.w = fmaxf(v.w + postb[gcol + 3], 0.f);
                }
                *(float4*)(C + (size_t)grow * Nout + gcol) = v;
            }
        }
    }
}

// ---------------- launch: ONLY kernel launches, no other CUDA API ----------------
extern "C" void kernel_launch(void* const* d_in, const int* in_sizes, int n_in,
                              void* d_out, int out_size) {
    const float* x   = (const float*)d_in[0];
    const void*  ei  = d_in[1];
    const float* Wg0 = (const float*)d_in[2];
    const float* bg0 = (const float*)d_in[3];
    const float* Wg1 = (const float*)d_in[4];
    const float* bg1 = (const float*)d_in[5];
    const float* Wg2 = (const float*)d_in[6];
    const float* bg2 = (const float*)d_in[7];
    const float* Wm0 = (const float*)d_in[8];
    const float* bm0 = (const float*)d_in[9];
    const float* Wm1 = (const float*)d_in[10];
    const float* bm1 = (const float*)d_in[11];
    float*       out = (float*)d_out;

    // --- CSR build ---
    detect_kernel<<<1, 32>>>(ei);
    zero_cnt_kernel<<<(NN + 256) / 256, 256>>>();
    hist_kernel<<<(EE + 255) / 256, 256>>>(ei);
    dinv_kernel<<<(NN + 255) / 256, 256>>>();
    scan1_kernel<<<SCAN_NB, SCAN_B>>>();
    scan2_kernel<<<1, 256>>>();
    scan3_kernel<<<SCAN_NB, SCAN_B>>>();
    fill_kernel<<<(EE + 255) / 256, 256>>>(ei);

    dim3 blk(256);
    const int MB = (NN + 127) / 128;
    dim3 g128(MB, 1);
    dim3 g512(MB, 4);
    dim3 g256(MB, 2);
    int aggBlocks = (NN * 32 + 255) / 256;

    // GCN layer 0
    gemm_kernel<128, false, false, 0, 1><<<g128, blk>>>(x, Wg0, nullptr, nullptr, nullptr, NN, HIDD);
    agg_kernel<<<aggBlocks, 256>>>();
    // GCN layer 1
    gemm_kernel<128, true, false, 2, 1><<<g128, blk>>>(nullptr, Wg1, bg0, nullptr, nullptr, NN, HIDD);
    agg_kernel<<<aggBlocks, 256>>>();
    // GCN layer 2
    gemm_kernel<128, true, false, 2, 1><<<g128, blk>>>(nullptr, Wg2, bg1, nullptr, nullptr, NN, HIDD);
    agg_kernel<<<aggBlocks, 256>>>();
    // MLP
    gemm_kernel<128, true, true, 2, 3><<<g512, blk>>>(nullptr, Wm0, bg2, bm0, nullptr, NN, MLP0);
    gemm_kernel<512, false, true, 3, 0><<<g256, blk>>>(nullptr, Wm1, nullptr, bm1, out, NN, MLP1);
}

// round 9
// speedup vs baseline: 2.1791x; 1.9752x over previous
#include <cuda_runtime.h>
#include <cuda_bf16.h>
#include <cstdint>

#define NN   50000
#define EE   800000
#define HIDD 128
#define MLP0 512
#define MLP1 256

// ---------------- scratch (device globals; referenced ONLY from device code) ----------------
__device__ float g_H[(size_t)NN * HIDD];
__device__ float g_AGG[(size_t)NN * HIDD];
__device__ float g_M1[(size_t)NN * MLP0];
__device__ int   g_cnt[NN + 1];
__device__ int   g_rowptr[NN + 1];
__device__ int   g_fill[NN];
__device__ float g_dinv[NN];
__device__ int   g_csr_src[EE];
__device__ float g_csr_w[EE];
__device__ int   g_is64;
__device__ int   g_bsum[256];
__device__ int   g_boff[256];

#define SCAN_B 256
#define SCAN_NB ((NN + SCAN_B - 1) / SCAN_B)   // 196

// ---------------- edge_index dtype detection ----------------
__global__ void detect_kernel(const void* __restrict__ ei) {
    if (threadIdx.x == 0 && blockIdx.x == 0) {
        const long long* p = (const long long*)ei;
        int ok = 1;
#pragma unroll
        for (int i = 0; i < 16; i++) {
            long long v = p[i];
            if (v < 0 || v >= NN) ok = 0;
        }
        g_is64 = ok;
    }
}

__device__ __forceinline__ int load_idx(const void* __restrict__ ei, int e, int which) {
    if (g_is64) return (int)((const long long*)ei)[(size_t)which * EE + e];
    return ((const int*)ei)[(size_t)which * EE + e];
}

// ---------------- CSR build ----------------
__global__ void zero_cnt_kernel() {
    int i = blockIdx.x * blockDim.x + threadIdx.x;
    if (i <= NN) g_cnt[i] = 0;
}

__global__ void hist_kernel(const void* __restrict__ ei) {
    int e = blockIdx.x * blockDim.x + threadIdx.x;
    if (e >= EE) return;
    unsigned d = (unsigned)load_idx(ei, e, 1);
    if (d < NN) atomicAdd(&g_cnt[d], 1);
}

__global__ void dinv_kernel() {
    int v = blockIdx.x * blockDim.x + threadIdx.x;
    if (v < NN) g_dinv[v] = rsqrtf((float)(g_cnt[v] + 1));
}

__global__ void scan1_kernel() {
    __shared__ int sh[SCAN_B];
    int t = threadIdx.x, i = blockIdx.x * SCAN_B + t;
    int v = (i < NN) ? g_cnt[i] : 0;
    sh[t] = v;
    __syncthreads();
    for (int off = 1; off < SCAN_B; off <<= 1) {
        int add = (t >= off) ? sh[t - off] : 0;
        __syncthreads();
        sh[t] += add;
        __syncthreads();
    }
    if (i < NN) g_rowptr[i] = sh[t] - v;
    if (t == SCAN_B - 1) g_bsum[blockIdx.x] = sh[SCAN_B - 1];
}

__global__ void scan2_kernel() {
    __shared__ int sh[256];
    int t = threadIdx.x;
    int v = (t < SCAN_NB) ? g_bsum[t] : 0;
    sh[t] = v;
    __syncthreads();
    for (int off = 1; off < 256; off <<= 1) {
        int add = (t >= off) ? sh[t - off] : 0;
        __syncthreads();
        sh[t] += add;
        __syncthreads();
    }
    if (t < SCAN_NB) g_boff[t] = sh[t] - v;
    if (t == 255) g_rowptr[NN] = sh[255];
}

__global__ void scan3_kernel() {
    int t = threadIdx.x, i = blockIdx.x * SCAN_B + t;
    if (i < NN) {
        int r = g_rowptr[i] + g_boff[blockIdx.x];
        g_rowptr[i] = r;
        g_fill[i]   = r;
    }
}

__global__ void fill_kernel(const void* __restrict__ ei) {
    int e = blockIdx.x * blockDim.x + threadIdx.x;
    if (e >= EE) return;
    unsigned s = (unsigned)load_idx(ei, e, 0);
    unsigned d = (unsigned)load_idx(ei, e, 1);
    if (s >= NN || d >= NN) return;
    int p = atomicAdd(&g_fill[d], 1);
    if (p < EE) {
        g_csr_src[p] = (int)s;
        g_csr_w[p]   = g_dinv[s] * g_dinv[d];
    }
}

// ---------------- pull aggregation: one warp per dst, 8-way edge unroll ----------------
__global__ void agg_kernel() {
    const float4* __restrict__ H4 = (const float4*)g_H;
    int gw   = (blockIdx.x * blockDim.x + threadIdx.x) >> 5;
    int lane = threadIdx.x & 31;
    if (gw >= NN) return;
    float sw = g_dinv[gw];
    sw *= sw;
    float4 a = H4[(size_t)gw * 32 + lane];
    a.x *= sw; a.y *= sw; a.z *= sw; a.w *= sw;
    int e = g_rowptr[gw], end = g_rowptr[gw + 1];

    for (; e + 8 <= end; e += 8) {
        int   s0 = g_csr_src[e + 0], s1 = g_csr_src[e + 1];
        int   s2 = g_csr_src[e + 2], s3 = g_csr_src[e + 3];
        int   s4 = g_csr_src[e + 4], s5 = g_csr_src[e + 5];
        int   s6 = g_csr_src[e + 6], s7 = g_csr_src[e + 7];
        float w0 = g_csr_w[e + 0], w1 = g_csr_w[e + 1];
        float w2 = g_csr_w[e + 2], w3 = g_csr_w[e + 3];
        float w4 = g_csr_w[e + 4], w5 = g_csr_w[e + 5];
        float w6 = g_csr_w[e + 6], w7 = g_csr_w[e + 7];
        float4 h0 = H4[(size_t)s0 * 32 + lane];
        float4 h1 = H4[(size_t)s1 * 32 + lane];
        float4 h2 = H4[(size_t)s2 * 32 + lane];
        float4 h3 = H4[(size_t)s3 * 32 + lane];
        float4 h4 = H4[(size_t)s4 * 32 + lane];
        float4 h5 = H4[(size_t)s5 * 32 + lane];
        float4 h6 = H4[(size_t)s6 * 32 + lane];
        float4 h7 = H4[(size_t)s7 * 32 + lane];
        a.x = fmaf(h0.x, w0, a.x); a.y = fmaf(h0.y, w0, a.y); a.z = fmaf(h0.z, w0, a.z); a.w = fmaf(h0.w, w0, a.w);
        a.x = fmaf(h1.x, w1, a.x); a.y = fmaf(h1.y, w1, a.y); a.z = fmaf(h1.z, w1, a.z); a.w = fmaf(h1.w, w1, a.w);
        a.x = fmaf(h2.x, w2, a.x); a.y = fmaf(h2.y, w2, a.y); a.z = fmaf(h2.z, w2, a.z); a.w = fmaf(h2.w, w2, a.w);
        a.x = fmaf(h3.x, w3, a.x); a.y = fmaf(h3.y, w3, a.y); a.z = fmaf(h3.z, w3, a.z); a.w = fmaf(h3.w, w3, a.w);
        a.x = fmaf(h4.x, w4, a.x); a.y = fmaf(h4.y, w4, a.y); a.z = fmaf(h4.z, w4, a.z); a.w = fmaf(h4.w, w4, a.w);
        a.x = fmaf(h5.x, w5, a.x); a.y = fmaf(h5.y, w5, a.y); a.z = fmaf(h5.z, w5, a.z); a.w = fmaf(h5.w, w5, a.w);
        a.x = fmaf(h6.x, w6, a.x); a.y = fmaf(h6.y, w6, a.y); a.z = fmaf(h6.z, w6, a.z); a.w = fmaf(h6.w, w6, a.w);
        a.x = fmaf(h7.x, w7, a.x); a.y = fmaf(h7.y, w7, a.y); a.z = fmaf(h7.z, w7, a.z); a.w = fmaf(h7.w, w7, a.w);
    }
    for (; e < end; e++) {
        int   s  = g_csr_src[e];
        float wv = g_csr_w[e];
        float4 h = H4[(size_t)s * 32 + lane];
        a.x = fmaf(h.x, wv, a.x);
        a.y = fmaf(h.y, wv, a.y);
        a.z = fmaf(h.z, wv, a.z);
        a.w = fmaf(h.w, wv, a.w);
    }
    ((float4*)g_AGG)[(size_t)gw * 32 + lane] = a;
}

// ================= tensor-core GEMM: split-bf16 (hi/lo), mma.sync m16n8k16 =================
__device__ __forceinline__ void ldsm4(uint32_t& r0, uint32_t& r1, uint32_t& r2, uint32_t& r3, uint32_t addr) {
    asm volatile("ldmatrix.sync.aligned.m8n8.x4.shared.b16 {%0,%1,%2,%3}, [%4];"
                 : "=r"(r0), "=r"(r1), "=r"(r2), "=r"(r3) : "r"(addr));
}
__device__ __forceinline__ void ldsm4t(uint32_t& r0, uint32_t& r1, uint32_t& r2, uint32_t& r3, uint32_t addr) {
    asm volatile("ldmatrix.sync.aligned.m8n8.x4.trans.shared.b16 {%0,%1,%2,%3}, [%4];"
                 : "=r"(r0), "=r"(r1), "=r"(r2), "=r"(r3) : "r"(addr));
}
__device__ __forceinline__ void mma16816(float* c, const uint32_t* a, uint32_t b0, uint32_t b1) {
    asm("mma.sync.aligned.m16n8k16.row.col.f32.bf16.bf16.f32 "
        "{%0,%1,%2,%3},{%4,%5,%6,%7},{%8,%9},{%0,%1,%2,%3};"
        : "+f"(c[0]), "+f"(c[1]), "+f"(c[2]), "+f"(c[3])
        : "r"(a[0]), "r"(a[1]), "r"(a[2]), "r"(a[3]), "r"(b0), "r"(b1));
}
// split v into hi+lo bf16; pack pairs (x,y) into u32 (x in low half)
__device__ __forceinline__ void split_pack(float x, float y, uint32_t& hi, uint32_t& lo) {
    __nv_bfloat16 hx = __float2bfloat16_rn(x);
    __nv_bfloat16 hy = __float2bfloat16_rn(y);
    float rx = x - __bfloat162float(hx);
    float ry = y - __bfloat162float(hy);
    __nv_bfloat16 lx = __float2bfloat16_rn(rx);
    __nv_bfloat16 ly = __float2bfloat16_rn(ry);
    hi = (uint32_t)__bfloat16_as_ushort(hx) | ((uint32_t)__bfloat16_as_ushort(hy) << 16);
    lo = (uint32_t)__bfloat16_as_ushort(lx) | ((uint32_t)__bfloat16_as_ushort(ly) << 16);
}

#define ASTRIDE 40    // 32 + 8 pad (bf16)  -> LDSM conflict-free
#define WSTRIDE 136   // 128 + 8 pad (bf16) -> LDSM.trans conflict-free

// C = act(A) @ W; 128x128x32 tiles, 8 warps (4 m x 2 n), 32x64 per warp.
// ASEL/CSEL: 0=arg, 1=g_H, 2=g_AGG, 3=g_M1. PRE: relu(A+preb) at load; POST: relu(C+postb).
template <int K, bool PRE, bool POST, int ASEL, int CSEL>
__global__ void __launch_bounds__(256, 2)
gemm_kernel(const float* __restrict__ Aarg, const float* __restrict__ W,
            const float* __restrict__ preb, const float* __restrict__ postb,
            float* __restrict__ Carg, int M, int Nout) {
    const float* A = (ASEL == 1) ? g_H : (ASEL == 2) ? g_AGG : (ASEL == 3) ? g_M1 : Aarg;
    float*       C = (CSEL == 1) ? g_H : (CSEL == 2) ? g_AGG : (CSEL == 3) ? g_M1 : Carg;

    __shared__ __nv_bfloat16 As_hi[128 * ASTRIDE];
    __shared__ __nv_bfloat16 As_lo[128 * ASTRIDE];
    __shared__ __nv_bfloat16 Ws_hi[32 * WSTRIDE];
    __shared__ __nv_bfloat16 Ws_lo[32 * WSTRIDE];

    const int tid  = threadIdx.x;
    const int lane = tid & 31;
    const int wid  = tid >> 5;
    const int wm   = wid & 3;          // warp row: 32*wm
    const int wn   = wid >> 2;         // warp col: 64*wn
    const int row0 = blockIdx.x * 128;
    const int col0 = blockIdx.y * 128;

    uint32_t sAhi = (uint32_t)__cvta_generic_to_shared(As_hi);
    uint32_t sAlo = (uint32_t)__cvta_generic_to_shared(As_lo);
    uint32_t sWhi = (uint32_t)__cvta_generic_to_shared(Ws_hi);
    uint32_t sWlo = (uint32_t)__cvta_generic_to_shared(Ws_lo);

    float acc[2][8][4];
#pragma unroll
    for (int i = 0; i < 2; i++)
#pragma unroll
        for (int j = 0; j < 8; j++)
#pragma unroll
            for (int q = 0; q < 4; q++) acc[i][j][q] = 0.f;

    // ldmatrix lane addressing (shared): row = (lane&7) + ((lane>>3)&1)*8 ; half = lane>>4
    const int lrow  = (lane & 7) + ((lane >> 3) & 1) * 8;
    const int lhalf = lane >> 4;   // 0 or 1

    for (int k0 = 0; k0 < K; k0 += 32) {
        // ---- load A tile (128x32), split bf16 ----
#pragma unroll
        for (int h = 0; h < 4; h++) {
            int idx = tid + h * 256;           // 0..1023
            int r  = idx >> 3;                 // 0..127
            int kq = idx & 7;                  // float4 chunk (4 k)
            int grow = row0 + r;
            float4 v = make_float4(0.f, 0.f, 0.f, 0.f);
            if (grow < M) v = *(const float4*)(A + (size_t)grow * K + k0 + kq * 4);
            if (PRE) {
                v.x = fmaxf(v.x + preb[k0 + kq * 4 + 0], 0.f);
                v.y = fmaxf(v.y + preb[k0 + kq * 4 + 1], 0.f);
                v.z = fmaxf(v.z + preb[k0 + kq * 4 + 2], 0.f);
                v.w = fmaxf(v.w + preb[k0 + kq * 4 + 3], 0.f);
            }
            uint32_t h01, l01, h23, l23;
            split_pack(v.x, v.y, h01, l01);
            split_pack(v.z, v.w, h23, l23);
            uint32_t* dhi = (uint32_t*)(As_hi + r * ASTRIDE + kq * 4);
            uint32_t* dlo = (uint32_t*)(As_lo + r * ASTRIDE + kq * 4);
            dhi[0] = h01; dhi[1] = h23;
            dlo[0] = l01; dlo[1] = l23;
        }
        // ---- load W tile (32x128), split bf16 ----
#pragma unroll
        for (int h = 0; h < 4; h++) {
            int idx = tid + h * 256;
            int r  = idx >> 5;                 // k row 0..31
            int cq = idx & 31;                 // float4 col chunk
            float4 v = *(const float4*)(W + (size_t)(k0 + r) * Nout + col0 + cq * 4);
            uint32_t h01, l01, h23, l23;
            split_pack(v.x, v.y, h01, l01);
            split_pack(v.z, v.w, h23, l23);
            uint32_t* dhi = (uint32_t*)(Ws_hi + r * WSTRIDE + cq * 4);
            uint32_t* dlo = (uint32_t*)(Ws_lo + r * WSTRIDE + cq * 4);
            dhi[0] = h01; dhi[1] = h23;
            dlo[0] = l01; dlo[1] = l23;
        }
        __syncthreads();

#pragma unroll
        for (int ks = 0; ks < 2; ks++) {       // two k16 steps
            uint32_t ah[2][4], al[2][4];
#pragma unroll
            for (int mt = 0; mt < 2; mt++) {
                int arow = wm * 32 + mt * 16 + lrow;
                int acol = ks * 16 + lhalf * 8;
                uint32_t addr_h = sAhi + (uint32_t)(arow * ASTRIDE + acol) * 2;
                uint32_t addr_l = sAlo + (uint32_t)(arow * ASTRIDE + acol) * 2;
                ldsm4(ah[mt][0], ah[mt][1], ah[mt][2], ah[mt][3], addr_h);
                ldsm4(al[mt][0], al[mt][1], al[mt][2], al[mt][3], addr_l);
            }
#pragma unroll
            for (int np = 0; np < 4; np++) {   // ntile pairs (16 cols)
                int wrow = ks * 16 + lrow;
                int wcol = wn * 64 + np * 16 + lhalf * 8;
                uint32_t addr_h = sWhi + (uint32_t)(wrow * WSTRIDE + wcol) * 2;
                uint32_t addr_l = sWlo + (uint32_t)(wrow * WSTRIDE + wcol) * 2;
                uint32_t bh[4], bl[4];
                ldsm4t(bh[0], bh[1], bh[2], bh[3], addr_h);
                ldsm4t(bl[0], bl[1], bl[2], bl[3], addr_l);
#pragma unroll
                for (int mt = 0; mt < 2; mt++) {
#pragma unroll
                    for (int nl = 0; nl < 2; nl++) {
                        float* c = acc[mt][np * 2 + nl];
                        mma16816(c, ah[mt], bh[nl * 2], bh[nl * 2 + 1]);   // hi*hi
                        mma16816(c, ah[mt], bl[nl * 2], bl[nl * 2 + 1]);   // hi*lo
                        mma16816(c, al[mt], bh[nl * 2], bh[nl * 2 + 1]);   // lo*hi
                    }
                }
            }
        }
        __syncthreads();
    }

    // ---- epilogue ----
    const int gi = lane >> 2;      // 0..7
    const int qi = lane & 3;       // 0..3
#pragma unroll
    for (int mt = 0; mt < 2; mt++) {
#pragma unroll
        for (int nt = 0; nt < 8; nt++) {
            float* c = acc[mt][nt];
            int col = col0 + wn * 64 + nt * 8 + qi * 2;
            int r0r = row0 + wm * 32 + mt * 16 + gi;
            float2 v0 = make_float2(c[0], c[1]);
            float2 v1 = make_float2(c[2], c[3]);
            if (POST) {
                float b0 = postb[col], b1 = postb[col + 1];
                v0.x = fmaxf(v0.x + b0, 0.f); v0.y = fmaxf(v0.y + b1, 0.f);
                v1.x = fmaxf(v1.x + b0, 0.f); v1.y = fmaxf(v1.y + b1, 0.f);
            }
            if (r0r < M)     *(float2*)(C + (size_t)r0r * Nout + col)       = v0;
            if (r0r + 8 < M) *(float2*)(C + (size_t)(r0r + 8) * Nout + col) = v1;
        }
    }
}

// ---------------- launch ----------------
extern "C" void kernel_launch(void* const* d_in, const int* in_sizes, int n_in,
                              void* d_out, int out_size) {
    const float* x   = (const float*)d_in[0];
    const void*  ei  = d_in[1];
    const float* Wg0 = (const float*)d_in[2];
    const float* bg0 = (const float*)d_in[3];
    const float* Wg1 = (const float*)d_in[4];
    const float* bg1 = (const float*)d_in[5];
    const float* Wg2 = (const float*)d_in[6];
    const float* bg2 = (const float*)d_in[7];
    const float* Wm0 = (const float*)d_in[8];
    const float* bm0 = (const float*)d_in[9];
    const float* Wm1 = (const float*)d_in[10];
    const float* bm1 = (const float*)d_in[11];
    float*       out = (float*)d_out;

    detect_kernel<<<1, 32>>>(ei);
    zero_cnt_kernel<<<(NN + 256) / 256, 256>>>();
    hist_kernel<<<(EE + 255) / 256, 256>>>(ei);
    dinv_kernel<<<(NN + 255) / 256, 256>>>();
    scan1_kernel<<<SCAN_NB, SCAN_B>>>();
    scan2_kernel<<<1, 256>>>();
    scan3_kernel<<<SCAN_NB, SCAN_B>>>();
    fill_kernel<<<(EE + 255) / 256, 256>>>(ei);

    dim3 blk(256);
    const int MB = (NN + 127) / 128;
    dim3 g128(MB, 1);
    dim3 g512(MB, 4);
    dim3 g256(MB, 2);
    int aggBlocks = (NN * 32 + 255) / 256;

    gemm_kernel<128, false, false, 0, 1><<<g128, blk>>>(x, Wg0, nullptr, nullptr, nullptr, NN, HIDD);
    agg_kernel<<<aggBlocks, 256>>>();
    gemm_kernel<128, true, false, 2, 1><<<g128, blk>>>(nullptr, Wg1, bg0, nullptr, nullptr, NN, HIDD);
    agg_kernel<<<aggBlocks, 256>>>();
    gemm_kernel<128, true, false, 2, 1><<<g128, blk>>>(nullptr, Wg2, bg1, nullptr, nullptr, NN, HIDD);
    agg_kernel<<<aggBlocks, 256>>>();
    gemm_kernel<128, true, true, 2, 3><<<g512, blk>>>(nullptr, Wm0, bg2, bm0, nullptr, NN, MLP0);
    gemm_kernel<512, false, true, 3, 0><<<g256, blk>>>(nullptr, Wm1, nullptr, bm1, out, NN, MLP1);
}

// round 10
// speedup vs baseline: 2.1840x; 1.0022x over previous
#include <cuda_runtime.h>
#include <cuda_bf16.h>
#include <cstdint>

#define NN   50000
#define EE   800000
#define HIDD 128
#define MLP0 512
#define MLP1 256

// weight arena offsets (elements)
#define WOFF_G0 0
#define WOFF_G1 16384
#define WOFF_G2 32768
#define WOFF_M0 49152
#define WOFF_M1 114688
#define WTOTAL  245760

// ---------------- scratch (device globals; referenced ONLY from device code) ----------------
__device__ float         g_H[(size_t)NN * HIDD];        // GEMM fp32 output (pre-agg)
__device__ __nv_bfloat16 g_Ahi[(size_t)NN * HIDD];      // activation split (GCN)
__device__ __nv_bfloat16 g_Alo[(size_t)NN * HIDD];
__device__ __nv_bfloat16 g_Bhi[(size_t)NN * MLP0];      // MLP hidden split
__device__ __nv_bfloat16 g_Blo[(size_t)NN * MLP0];
__device__ __nv_bfloat16 g_Wshi[WTOTAL];
__device__ __nv_bfloat16 g_Wslo[WTOTAL];
__device__ int   g_cnt[NN + 1];
__device__ int   g_rowptr[NN + 1];
__device__ int   g_fill[NN];
__device__ float g_dinv[NN];
__device__ int   g_csr_src[EE];
__device__ float g_csr_w[EE];
__device__ int   g_is64;
__device__ int   g_bsum[256];
__device__ int   g_boff[256];

#define SCAN_B 256
#define SCAN_NB ((NN + SCAN_B - 1) / SCAN_B)   // 196

// ---------------- helpers ----------------
__device__ __forceinline__ void split_pack(float x, float y, uint32_t& hi, uint32_t& lo) {
    __nv_bfloat16 hx = __float2bfloat16_rn(x);
    __nv_bfloat16 hy = __float2bfloat16_rn(y);
    float rx = x - __bfloat162float(hx);
    float ry = y - __bfloat162float(hy);
    __nv_bfloat16 lx = __float2bfloat16_rn(rx);
    __nv_bfloat16 ly = __float2bfloat16_rn(ry);
    hi = (uint32_t)__bfloat16_as_ushort(hx) | ((uint32_t)__bfloat16_as_ushort(hy) << 16);
    lo = (uint32_t)__bfloat16_as_ushort(lx) | ((uint32_t)__bfloat16_as_ushort(ly) << 16);
}

// ---------------- edge_index dtype detection ----------------
__global__ void detect_kernel(const void* __restrict__ ei) {
    if (threadIdx.x == 0 && blockIdx.x == 0) {
        const long long* p = (const long long*)ei;
        int ok = 1;
#pragma unroll
        for (int i = 0; i < 16; i++) {
            long long v = p[i];
            if (v < 0 || v >= NN) ok = 0;
        }
        g_is64 = ok;
    }
}

__device__ __forceinline__ int load_idx(const void* __restrict__ ei, int e, int which) {
    if (g_is64) return (int)((const long long*)ei)[(size_t)which * EE + e];
    return ((const int*)ei)[(size_t)which * EE + e];
}

// ---------------- CSR build ----------------
__global__ void zero_cnt_kernel() {
    int i = blockIdx.x * blockDim.x + threadIdx.x;
    if (i <= NN) g_cnt[i] = 0;
}

__global__ void hist_kernel(const void* __restrict__ ei) {
    int e = blockIdx.x * blockDim.x + threadIdx.x;
    if (e >= EE) return;
    unsigned d = (unsigned)load_idx(ei, e, 1);
    if (d < NN) atomicAdd(&g_cnt[d], 1);
}

__global__ void dinv_kernel() {
    int v = blockIdx.x * blockDim.x + threadIdx.x;
    if (v < NN) g_dinv[v] = rsqrtf((float)(g_cnt[v] + 1));
}

__global__ void scan1_kernel() {
    __shared__ int sh[SCAN_B];
    int t = threadIdx.x, i = blockIdx.x * SCAN_B + t;
    int v = (i < NN) ? g_cnt[i] : 0;
    sh[t] = v;
    __syncthreads();
    for (int off = 1; off < SCAN_B; off <<= 1) {
        int add = (t >= off) ? sh[t - off] : 0;
        __syncthreads();
        sh[t] += add;
        __syncthreads();
    }
    if (i < NN) g_rowptr[i] = sh[t] - v;
    if (t == SCAN_B - 1) g_bsum[blockIdx.x] = sh[SCAN_B - 1];
}

__global__ void scan2_kernel() {
    __shared__ int sh[256];
    int t = threadIdx.x;
    int v = (t < SCAN_NB) ? g_bsum[t] : 0;
    sh[t] = v;
    __syncthreads();
    for (int off = 1; off < 256; off <<= 1) {
        int add = (t >= off) ? sh[t - off] : 0;
        __syncthreads();
        sh[t] += add;
        __syncthreads();
    }
    if (t < SCAN_NB) g_boff[t] = sh[t] - v;
    if (t == 255) g_rowptr[NN] = sh[255];
}

__global__ void scan3_kernel() {
    int t = threadIdx.x, i = blockIdx.x * SCAN_B + t;
    if (i < NN) {
        int r = g_rowptr[i] + g_boff[blockIdx.x];
        g_rowptr[i] = r;
        g_fill[i]   = r;
    }
}

__global__ void fill_kernel(const void* __restrict__ ei) {
    int e = blockIdx.x * blockDim.x + threadIdx.x;
    if (e >= EE) return;
    unsigned s = (unsigned)load_idx(ei, e, 0);
    unsigned d = (unsigned)load_idx(ei, e, 1);
    if (s >= NN || d >= NN) return;
    int p = atomicAdd(&g_fill[d], 1);
    if (p < EE) {
        g_csr_src[p] = (int)s;
        g_csr_w[p]   = g_dinv[s] * g_dinv[d];
    }
}

// ---------------- conversion kernels (once per launch) ----------------
__global__ void conv_w_kernel(const float* __restrict__ src, int n4, int off) {
    int i = blockIdx.x * blockDim.x + threadIdx.x;
    if (i >= n4) return;
    float4 v = ((const float4*)src)[i];
    uint2 hi, lo;
    split_pack(v.x, v.y, hi.x, lo.x);
    split_pack(v.z, v.w, hi.y, lo.y);
    ((uint2*)(g_Wshi + off))[i] = hi;
    ((uint2*)(g_Wslo + off))[i] = lo;
}

__global__ void conv_x_kernel(const float* __restrict__ x) {
    int i = blockIdx.x * blockDim.x + threadIdx.x;
    if (i >= NN * HIDD / 4) return;
    float4 v = ((const float4*)x)[i];
    uint2 hi, lo;
    split_pack(v.x, v.y, hi.x, lo.x);
    split_pack(v.z, v.w, hi.y, lo.y);
    ((uint2*)g_Ahi)[i] = hi;
    ((uint2*)g_Alo)[i] = lo;
}

// ---------------- pull aggregation + fused bias/ReLU/split ----------------
// g_A{hi,lo}[v] = split( relu( dinv^2*H[v] + sum_e w_e*H[src_e] + bias ) )
__global__ void agg_kernel(const float* __restrict__ bias) {
    const float4* __restrict__ H4 = (const float4*)g_H;
    int gw   = (blockIdx.x * blockDim.x + threadIdx.x) >> 5;
    int lane = threadIdx.x & 31;
    if (gw >= NN) return;
    float sw = g_dinv[gw];
    sw *= sw;
    float4 a = H4[(size_t)gw * 32 + lane];
    a.x *= sw; a.y *= sw; a.z *= sw; a.w *= sw;
    int e = g_rowptr[gw], end = g_rowptr[gw + 1];

    for (; e + 8 <= end; e += 8) {
        int   s0 = g_csr_src[e + 0], s1 = g_csr_src[e + 1];
        int   s2 = g_csr_src[e + 2], s3 = g_csr_src[e + 3];
        int   s4 = g_csr_src[e + 4], s5 = g_csr_src[e + 5];
        int   s6 = g_csr_src[e + 6], s7 = g_csr_src[e + 7];
        float w0 = g_csr_w[e + 0], w1 = g_csr_w[e + 1];
        float w2 = g_csr_w[e + 2], w3 = g_csr_w[e + 3];
        float w4 = g_csr_w[e + 4], w5 = g_csr_w[e + 5];
        float w6 = g_csr_w[e + 6], w7 = g_csr_w[e + 7];
        float4 h0 = H4[(size_t)s0 * 32 + lane];
        float4 h1 = H4[(size_t)s1 * 32 + lane];
        float4 h2 = H4[(size_t)s2 * 32 + lane];
        float4 h3 = H4[(size_t)s3 * 32 + lane];
        float4 h4 = H4[(size_t)s4 * 32 + lane];
        float4 h5 = H4[(size_t)s5 * 32 + lane];
        float4 h6 = H4[(size_t)s6 * 32 + lane];
        float4 h7 = H4[(size_t)s7 * 32 + lane];
        a.x = fmaf(h0.x, w0, a.x); a.y = fmaf(h0.y, w0, a.y); a.z = fmaf(h0.z, w0, a.z); a.w = fmaf(h0.w, w0, a.w);
        a.x = fmaf(h1.x, w1, a.x); a.y = fmaf(h1.y, w1, a.y); a.z = fmaf(h1.z, w1, a.z); a.w = fmaf(h1.w, w1, a.w);
        a.x = fmaf(h2.x, w2, a.x); a.y = fmaf(h2.y, w2, a.y); a.z = fmaf(h2.z, w2, a.z); a.w = fmaf(h2.w, w2, a.w);
        a.x = fmaf(h3.x, w3, a.x); a.y = fmaf(h3.y, w3, a.y); a.z = fmaf(h3.z, w3, a.z); a.w = fmaf(h3.w, w3, a.w);
        a.x = fmaf(h4.x, w4, a.x); a.y = fmaf(h4.y, w4, a.y); a.z = fmaf(h4.z, w4, a.z); a.w = fmaf(h4.w, w4, a.w);
        a.x = fmaf(h5.x, w5, a.x); a.y = fmaf(h5.y, w5, a.y); a.z = fmaf(h5.z, w5, a.z); a.w = fmaf(h5.w, w5, a.w);
        a.x = fmaf(h6.x, w6, a.x); a.y = fmaf(h6.y, w6, a.y); a.z = fmaf(h6.z, w6, a.z); a.w = fmaf(h6.w, w6, a.w);
        a.x = fmaf(h7.x, w7, a.x); a.y = fmaf(h7.y, w7, a.y); a.z = fmaf(h7.z, w7, a.z); a.w = fmaf(h7.w, w7, a.w);
    }
    for (; e < end; e++) {
        int   s  = g_csr_src[e];
        float wv = g_csr_w[e];
        float4 h = H4[(size_t)s * 32 + lane];
        a.x = fmaf(h.x, wv, a.x);
        a.y = fmaf(h.y, wv, a.y);
        a.z = fmaf(h.z, wv, a.z);
        a.w = fmaf(h.w, wv, a.w);
    }
    const float4 b4 = ((const float4*)bias)[lane];
    a.x = fmaxf(a.x + b4.x, 0.f);
    a.y = fmaxf(a.y + b4.y, 0.f);
    a.z = fmaxf(a.z + b4.z, 0.f);
    a.w = fmaxf(a.w + b4.w, 0.f);
    uint2 hi, lo;
    split_pack(a.x, a.y, hi.x, lo.x);
    split_pack(a.z, a.w, hi.y, lo.y);
    ((uint2*)g_Ahi)[(size_t)gw * 32 + lane] = hi;
    ((uint2*)g_Alo)[(size_t)gw * 32 + lane] = lo;
}

// ================= tensor-core GEMM on pre-split bf16 =================
__device__ __forceinline__ void ldsm4(uint32_t& r0, uint32_t& r1, uint32_t& r2, uint32_t& r3, uint32_t addr) {
    asm volatile("ldmatrix.sync.aligned.m8n8.x4.shared.b16 {%0,%1,%2,%3}, [%4];"
                 : "=r"(r0), "=r"(r1), "=r"(r2), "=r"(r3) : "r"(addr));
}
__device__ __forceinline__ void ldsm4t(uint32_t& r0, uint32_t& r1, uint32_t& r2, uint32_t& r3, uint32_t addr) {
    asm volatile("ldmatrix.sync.aligned.m8n8.x4.trans.shared.b16 {%0,%1,%2,%3}, [%4];"
                 : "=r"(r0), "=r"(r1), "=r"(r2), "=r"(r3) : "r"(addr));
}
__device__ __forceinline__ void mma16816(float* c, const uint32_t* a, uint32_t b0, uint32_t b1) {
    asm("mma.sync.aligned.m16n8k16.row.col.f32.bf16.bf16.f32 "
        "{%0,%1,%2,%3},{%4,%5,%6,%7},{%8,%9},{%0,%1,%2,%3};"
        : "+f"(c[0]), "+f"(c[1]), "+f"(c[2]), "+f"(c[3])
        : "r"(a[0]), "r"(a[1]), "r"(a[2]), "r"(a[3]), "r"(b0), "r"(b1));
}

#define ASTRIDE 40    // bf16 elems; 80B row -> LDSM conflict-free
#define WSTRIDE 136   // bf16 elems; 272B row

// 128x128x32 tiles, 8 warps (4m x 2n), 32x64/warp, 3-MMA split product.
// ASEL: 0 = g_A (K=HIDD), 1 = g_B (K=MLP0).
// OUT:  0 = fp32 -> g_H (no post), 1 = bias+relu+split -> g_B, 2 = bias+relu fp32 -> Cout.
template <int K, int ASEL, int OUT>
__global__ void __launch_bounds__(256, 2)
gemm_tc(const float* __restrict__ bias, float* __restrict__ Cout, int M, int Nout, int woff) {
    const __nv_bfloat16* Ahi = (ASEL == 0) ? g_Ahi : g_Bhi;
    const __nv_bfloat16* Alo = (ASEL == 0) ? g_Alo : g_Blo;
    const __nv_bfloat16* Whi = g_Wshi + woff;
    const __nv_bfloat16* Wlo = g_Wslo + woff;

    __shared__ __nv_bfloat16 As_hi[128 * ASTRIDE];
    __shared__ __nv_bfloat16 As_lo[128 * ASTRIDE];
    __shared__ __nv_bfloat16 Ws_hi[32 * WSTRIDE];
    __shared__ __nv_bfloat16 Ws_lo[32 * WSTRIDE];

    const int tid  = threadIdx.x;
    const int lane = tid & 31;
    const int wid  = tid >> 5;
    const int wm   = wid & 3;
    const int wn   = wid >> 2;
    const int row0 = blockIdx.x * 128;
    const int col0 = blockIdx.y * 128;

    uint32_t sAhi = (uint32_t)__cvta_generic_to_shared(As_hi);
    uint32_t sAlo = (uint32_t)__cvta_generic_to_shared(As_lo);
    uint32_t sWhi = (uint32_t)__cvta_generic_to_shared(Ws_hi);
    uint32_t sWlo = (uint32_t)__cvta_generic_to_shared(Ws_lo);

    float acc[2][8][4];
#pragma unroll
    for (int i = 0; i < 2; i++)
#pragma unroll
        for (int j = 0; j < 8; j++)
#pragma unroll
            for (int q = 0; q < 4; q++) acc[i][j][q] = 0.f;

    const int lrow  = (lane & 7) + ((lane >> 3) & 1) * 8;
    const int lhalf = lane >> 4;

    for (int k0 = 0; k0 < K; k0 += 32) {
        // A tile: 128x32 bf16, hi+lo. 4 uint4 chunks per row; 2 rows' worth per thread pass.
#pragma unroll
        for (int h = 0; h < 2; h++) {
            int idx = tid + h * 256;          // 0..511
            int r  = idx >> 2;                // 0..127
            int kq = idx & 3;                 // uint4 chunk (8 bf16)
            int grow = row0 + r;
            uint4 vh = make_uint4(0, 0, 0, 0), vl = make_uint4(0, 0, 0, 0);
            if (grow < M) {
                size_t off = ((size_t)grow * K + k0 + kq * 8) >> 3;  // uint4 index
                vh = ((const uint4*)Ahi)[off];
                vl = ((const uint4*)Alo)[off];
            }
            *(uint4*)(As_hi + r * ASTRIDE + kq * 8) = vh;
            *(uint4*)(As_lo + r * ASTRIDE + kq * 8) = vl;
        }
        // W tile: 32x128 bf16, hi+lo. 16 uint4 chunks per row.
#pragma unroll
        for (int h = 0; h < 2; h++) {
            int idx = tid + h * 256;          // 0..511
            int r  = idx >> 4;                // 0..31
            int cq = idx & 15;                // uint4 chunk
            size_t off = ((size_t)(k0 + r) * Nout + col0 + cq * 8) >> 3;
            uint4 vh = ((const uint4*)Whi)[off];
            uint4 vl = ((const uint4*)Wlo)[off];
            *(uint4*)(Ws_hi + r * WSTRIDE + cq * 8) = vh;
            *(uint4*)(Ws_lo + r * WSTRIDE + cq * 8) = vl;
        }
        __syncthreads();

#pragma unroll
        for (int ks = 0; ks < 2; ks++) {
            uint32_t ah[2][4], al[2][4];
#pragma unroll
            for (int mt = 0; mt < 2; mt++) {
                int arow = wm * 32 + mt * 16 + lrow;
                int acol = ks * 16 + lhalf * 8;
                ldsm4(ah[mt][0], ah[mt][1], ah[mt][2], ah[mt][3], sAhi + (uint32_t)(arow * ASTRIDE + acol) * 2);
                ldsm4(al[mt][0], al[mt][1], al[mt][2], al[mt][3], sAlo + (uint32_t)(arow * ASTRIDE + acol) * 2);
            }
#pragma unroll
            for (int np = 0; np < 4; np++) {
                int wrow = ks * 16 + lrow;
                int wcol = wn * 64 + np * 16 + lhalf * 8;
                uint32_t bh[4], bl[4];
                ldsm4t(bh[0], bh[1], bh[2], bh[3], sWhi + (uint32_t)(wrow * WSTRIDE + wcol) * 2);
                ldsm4t(bl[0], bl[1], bl[2], bl[3], sWlo + (uint32_t)(wrow * WSTRIDE + wcol) * 2);
#pragma unroll
                for (int mt = 0; mt < 2; mt++) {
#pragma unroll
                    for (int nl = 0; nl < 2; nl++) {
                        float* c = acc[mt][np * 2 + nl];
                        mma16816(c, ah[mt], bh[nl * 2], bh[nl * 2 + 1]);
                        mma16816(c, ah[mt], bl[nl * 2], bl[nl * 2 + 1]);
                        mma16816(c, al[mt], bh[nl * 2], bh[nl * 2 + 1]);
                    }
                }
            }
        }
        __syncthreads();
    }

    // ---- epilogue ----
    const int gi = lane >> 2;
    const int qi = lane & 3;
#pragma unroll
    for (int mt = 0; mt < 2; mt++) {
#pragma unroll
        for (int nt = 0; nt < 8; nt++) {
            float* c = acc[mt][nt];
            int col  = col0 + wn * 64 + nt * 8 + qi * 2;
            int r0r  = row0 + wm * 32 + mt * 16 + gi;
            float2 v0 = make_float2(c[0], c[1]);
            float2 v1 = make_float2(c[2], c[3]);
            if (OUT != 0) {
                float b0 = bias[col], b1 = bias[col + 1];
                v0.x = fmaxf(v0.x + b0, 0.f); v0.y = fmaxf(v0.y + b1, 0.f);
                v1.x = fmaxf(v1.x + b0, 0.f); v1.y = fmaxf(v1.y + b1, 0.f);
            }
            if (OUT == 0) {
                if (r0r < M)     *(float2*)(g_H + (size_t)r0r * Nout + col)       = v0;
                if (r0r + 8 < M) *(float2*)(g_H + (size_t)(r0r + 8) * Nout + col) = v1;
            } else if (OUT == 1) {
                uint32_t hi0, lo0, hi1, lo1;
                split_pack(v0.x, v0.y, hi0, lo0);
                split_pack(v1.x, v1.y, hi1, lo1);
                if (r0r < M) {
                    *(uint32_t*)(g_Bhi + (size_t)r0r * Nout + col) = hi0;
                    *(uint32_t*)(g_Blo + (size_t)r0r * Nout + col) = lo0;
                }
                if (r0r + 8 < M) {
                    *(uint32_t*)(g_Bhi + (size_t)(r0r + 8) * Nout + col) = hi1;
                    *(uint32_t*)(g_Blo + (size_t)(r0r + 8) * Nout + col) = lo1;
                }
            } else {
                if (r0r < M)     *(float2*)(Cout + (size_t)r0r * Nout + col)       = v0;
                if (r0r + 8 < M) *(float2*)(Cout + (size_t)(r0r + 8) * Nout + col) = v1;
            }
        }
    }
}

// ---------------- launch ----------------
extern "C" void kernel_launch(void* const* d_in, const int* in_sizes, int n_in,
                              void* d_out, int out_size) {
    const float* x   = (const float*)d_in[0];
    const void*  ei  = d_in[1];
    const float* Wg0 = (const float*)d_in[2];
    const float* bg0 = (const float*)d_in[3];
    const float* Wg1 = (const float*)d_in[4];
    const float* bg1 = (const float*)d_in[5];
    const float* Wg2 = (const float*)d_in[6];
    const float* bg2 = (const float*)d_in[7];
    const float* Wm0 = (const float*)d_in[8];
    const float* bm0 = (const float*)d_in[9];
    const float* Wm1 = (const float*)d_in[10];
    const float* bm1 = (const float*)d_in[11];
    float*       out = (float*)d_out;

    // --- CSR build ---
    detect_kernel<<<1, 32>>>(ei);
    zero_cnt_kernel<<<(NN + 256) / 256, 256>>>();
    hist_kernel<<<(EE + 255) / 256, 256>>>(ei);
    dinv_kernel<<<(NN + 255) / 256, 256>>>();
    scan1_kernel<<<SCAN_NB, SCAN_B>>>();
    scan2_kernel<<<1, 256>>>();
    scan3_kernel<<<SCAN_NB, SCAN_B>>>();
    fill_kernel<<<(EE + 255) / 256, 256>>>(ei);

    // --- one-time conversions ---
    conv_w_kernel<<<(16384 / 4 + 255) / 256, 256>>>(Wg0, 16384 / 4, WOFF_G0);
    conv_w_kernel<<<(16384 / 4 + 255) / 256, 256>>>(Wg1, 16384 / 4, WOFF_G1);
    conv_w_kernel<<<(16384 / 4 + 255) / 256, 256>>>(Wg2, 16384 / 4, WOFF_G2);
    conv_w_kernel<<<(65536 / 4 + 255) / 256, 256>>>(Wm0, 65536 / 4, WOFF_M0);
    conv_w_kernel<<<(131072 / 4 + 255) / 256, 256>>>(Wm1, 131072 / 4, WOFF_M1);
    conv_x_kernel<<<(NN * HIDD / 4 + 255) / 256, 256>>>(x);

    dim3 blk(256);
    const int MB = (NN + 127) / 128;
    dim3 g128(MB, 1);
    dim3 g512(MB, 4);
    dim3 g256(MB, 2);
    int aggBlocks = (NN * 32 + 255) / 256;

    // GCN layers
    gemm_tc<128, 0, 0><<<g128, blk>>>(nullptr, nullptr, NN, HIDD, WOFF_G0);
    agg_kernel<<<aggBlocks, 256>>>(bg0);
    gemm_tc<128, 0, 0><<<g128, blk>>>(nullptr, nullptr, NN, HIDD, WOFF_G1);
    agg_kernel<<<aggBlocks, 256>>>(bg1);
    gemm_tc<128, 0, 0><<<g128, blk>>>(nullptr, nullptr, NN, HIDD, WOFF_G2);
    agg_kernel<<<aggBlocks, 256>>>(bg2);
    // MLP head
    gemm_tc<128, 0, 1><<<g512, blk>>>(bm0, nullptr, NN, MLP0, WOFF_M0);
    gemm_tc<512, 1, 2><<<g256, blk>>>(bm1, out, NN, MLP1, WOFF_M1);
}